// round 7
// baseline (speedup 1.0000x reference)
#include <cuda_runtime.h>
#include <math.h>

#define TOT   65536
#define NB    64
#define NPG   1024
#define NE    2097152
#define INCH  128
#define HID   32
#define KC    16
#define OUTC  10

// ---------------- scratch (static device globals; no allocation) ----------------
__device__ float g_h  [TOT*HID];    // lin1 output
__device__ float g_h1 [TOT*HID];    // conv1 output
__device__ float g_s  [TOT*KC];     // softmax assignments
__device__ float g_deg[TOT];        // out-degree per node (float)
__device__ int   g_cnt[TOT];        // degree counts (int) -- zeroed by k6 tail
__device__ int   g_off[TOT];        // CSR row offsets
__device__ int   g_bsum[64];        // scan block sums
__device__ int   g_bincur[128];     // per-bin bucket cursors
__device__ int   g_eb [NE];         // bin-bucketed packed edges (src&511)<<10 | (dst&1023)
__device__ unsigned short g_csr16[NE]; // node-sorted local dst (10 bits)
__device__ float g_out[NB*KC*HID];  // pooled features S^T H
__device__ float g_oa [NB*KC*KC];   // pooled adjacency S^T A S
__device__ float g_ss [NB*KC*KC];   // S^T S
__device__ float g_den[NB];         // tr(S^T D S)

__device__ __forceinline__ void redi(int* p, int v){
  asm volatile("red.global.add.s32 [%0], %1;" :: "l"(p), "r"(v) : "memory");
}

// ---------------- K1 (fat): degree REDG + h = x @ W1^T + b1 + zero pooled scratch ----------------
__global__ void __launch_bounds__(256) k1(const float* __restrict__ x,
                                          const float* __restrict__ W1,
                                          const float* __restrict__ b1,
                                          const int* __restrict__ ei,
                                          float* __restrict__ out){
  __shared__ float sW[INCH*HID];   // sW[i*32+j] = W1[j*128+i]
  __shared__ float sb[HID];
  int tid = threadIdx.x;

  // fire-and-forget degree counts for this block's 4096-edge share
  {
    const int4* e4 = reinterpret_cast<const int4*>(ei) + blockIdx.x*1024;
    #pragma unroll
    for (int q = 0; q < 4; q++){
      int4 s = __ldg(e4 + q*256 + tid);
      redi(g_cnt + s.x, 1);
      redi(g_cnt + s.y, 1);
      redi(g_cnt + s.z, 1);
      redi(g_cnt + s.w, 1);
    }
  }

  for (int u = tid; u < INCH*HID; u += 256){
    int i = u >> 5, j = u & 31;
    sW[u] = W1[j*INCH + i];
  }
  if (tid < HID) sb[tid] = b1[tid];

  int gid = blockIdx.x*256 + tid;
  if (gid < NB*KC*HID) g_out[gid] = 0.f;
  if (gid < NB*KC*KC){ g_oa[gid] = 0.f; g_ss[gid] = 0.f; }
  if (gid < NB) g_den[gid] = 0.f;
  if (gid == 0){ out[NB*OUTC] = 0.f; out[NB*OUTC+1] = 0.f; }
  __syncthreads();

  int base = blockIdx.x * 128;
  int rg = tid >> 3;
  int cg = tid & 7;
  int r0 = base + rg*4;

  float acc[4][4];
  #pragma unroll
  for (int k = 0; k < 4; k++)
    #pragma unroll
    for (int c = 0; c < 4; c++) acc[k][c] = sb[cg*4 + c];

  #pragma unroll 4
  for (int i4 = 0; i4 < 32; i4++){
    float4 xq[4];
    #pragma unroll
    for (int k = 0; k < 4; k++)
      xq[k] = __ldg(reinterpret_cast<const float4*>(x + (size_t)(r0+k)*INCH) + i4);
    #pragma unroll
    for (int ii = 0; ii < 4; ii++){
      int i = i4*4 + ii;
      float wv[4];
      #pragma unroll
      for (int c = 0; c < 4; c++) wv[c] = sW[i*32 + cg*4 + c];
      #pragma unroll
      for (int k = 0; k < 4; k++){
        float xs = (&xq[k].x)[ii];
        #pragma unroll
        for (int c = 0; c < 4; c++) acc[k][c] += xs * wv[c];
      }
    }
  }
  float4* h4 = reinterpret_cast<float4*>(g_h);
  #pragma unroll
  for (int k = 0; k < 4; k++)
    h4[(size_t)(r0+k)*8 + cg] = make_float4(acc[k][0],acc[k][1],acc[k][2],acc[k][3]);
}

// ---------------- kscanA: 64 blocks, local exclusive scan of 1024 counts each ----------------
__global__ void __launch_bounds__(256) kscanA(){
  int tid = threadIdx.x, blk = blockIdx.x;
  int i4 = blk*256 + tid;
  int4 c = __ldg(reinterpret_cast<const int4*>(g_cnt) + i4);
  int s = c.x + c.y + c.z + c.w;
  int lane = tid & 31, wid = tid >> 5;
  int v = s;
  #pragma unroll
  for (int o = 1; o < 32; o <<= 1){
    int t = __shfl_up_sync(0xffffffffu, v, o);
    if (lane >= o) v += t;
  }
  __shared__ int wsum[8];
  if (lane == 31) wsum[wid] = v;
  __syncthreads();
  int wpfx = 0;
  if (wid > 0){
    #pragma unroll
    for (int w = 0; w < 7; w++) if (w < wid) wpfx += wsum[w];
  }
  int base = v - s + wpfx;
  int4 o;
  o.x = base; o.y = base + c.x; o.z = o.y + c.y; o.w = o.z + c.z;
  reinterpret_cast<int4*>(g_off)[i4] = o;
  reinterpret_cast<float4*>(g_deg)[i4] = make_float4((float)c.x,(float)c.y,(float)c.z,(float)c.w);
  if (tid == 255) g_bsum[blk] = o.w + c.w;
}

// ---------------- kscanC: add block prefix (computed redundantly), init bin cursors ----------------
__global__ void __launch_bounds__(256) kscanC(){
  int tid = threadIdx.x, blk = blockIdx.x;
  __shared__ int spfx;
  if (tid < 32){
    int a = __ldg(g_bsum + tid), b2 = __ldg(g_bsum + tid + 32);
    int v = ((tid < blk) ? a : 0) + ((tid + 32 < blk) ? b2 : 0);
    #pragma unroll
    for (int o = 16; o > 0; o >>= 1) v += __shfl_xor_sync(0xffffffffu, v, o);
    if (tid == 0) spfx = v;
  }
  __syncthreads();
  int p = spfx;
  int i4 = blk*256 + tid;
  int4 o = reinterpret_cast<const int4*>(g_off)[i4];
  o.x += p; o.y += p; o.z += p; o.w += p;
  reinterpret_cast<int4*>(g_off)[i4] = o;
  if (tid == 0)   g_bincur[2*blk]     = o.x;   // node blk*1024
  if (tid == 128) g_bincur[2*blk + 1] = o.x;   // node blk*1024 + 512
}

// ---------------- kb2: bucket edges by 512-node bin (bin = src>>9) ----------------
__global__ void __launch_bounds__(256) kb2(const int* __restrict__ ei){
  __shared__ int hist[128], scur[128];
  int tid = threadIdx.x, blk = blockIdx.x;
  if (tid < 128) hist[tid] = 0;
  __syncthreads();
  const int4* s4p = reinterpret_cast<const int4*>(ei) + blk*1024;
  const int4* d4p = reinterpret_cast<const int4*>(ei) + NE/4 + blk*1024;
  #pragma unroll
  for (int q = 0; q < 4; q++){
    int4 s = __ldg(s4p + q*256 + tid);
    atomicAdd(&hist[s.x >> 9], 1);
    atomicAdd(&hist[s.y >> 9], 1);
    atomicAdd(&hist[s.z >> 9], 1);
    atomicAdd(&hist[s.w >> 9], 1);
  }
  __syncthreads();
  if (tid < 128) scur[tid] = atomicAdd(&g_bincur[tid], hist[tid]);
  __syncthreads();
  #pragma unroll
  for (int q = 0; q < 4; q++){
    int4 s = __ldg(s4p + q*256 + tid);
    int4 d = __ldg(d4p + q*256 + tid);
    int p0 = atomicAdd(&scur[s.x >> 9], 1);
    int p1 = atomicAdd(&scur[s.y >> 9], 1);
    int p2 = atomicAdd(&scur[s.z >> 9], 1);
    int p3 = atomicAdd(&scur[s.w >> 9], 1);
    g_eb[p0] = ((s.x & 511) << 10) | (d.x & 1023);
    g_eb[p1] = ((s.y & 511) << 10) | (d.y & 1023);
    g_eb[p2] = ((s.z & 511) << 10) | (d.z & 1023);
    g_eb[p3] = ((s.w & 511) << 10) | (d.w & 1023);
  }
}

// ---------------- kfill2: node-sort within bin via smem cursors ----------------
__global__ void __launch_bounds__(1024) kfill2(){
  __shared__ int scur[512];
  int tid = threadIdx.x, bin = blockIdx.x;
  int node0 = bin*512;
  if (tid < 512) scur[tid] = __ldg(g_off + node0 + tid);
  __syncthreads();
  int e0 = __ldg(g_off + node0);
  int e1 = (bin < 127) ? __ldg(g_off + node0 + 512) : NE;
  for (int e = e0 + tid; e < e1; e += 1024){
    int p = __ldg(g_eb + e);
    int sl = p >> 10, dl = p & 1023;
    int pos = atomicAdd(&scur[sl], 1);
    g_csr16[pos] = (unsigned short)dl;
  }
}

// ---------------- K2s: smem-staged gather + conv1 + pool-softmax ----------------
#define SMEM2 ((1024*33 + 512*33 + 1024 + 1024 + 512 + 32 + 16) * 4)
__global__ void __launch_bounds__(1024, 1) k2s(const float* __restrict__ Wrel1,
                                               const float* __restrict__ brel1,
                                               const float* __restrict__ Wroot1,
                                               const float* __restrict__ Wp,
                                               const float* __restrict__ bp){
  extern __shared__ float smem[];
  float* sH   = smem;              // 1024*33
  float* sAgg = sH + 1024*33;      // 512*33
  float* sWr  = sAgg + 512*33;     // 32*32
  float* sWo  = sWr + 1024;        // 32*32
  float* sWp  = sWo + 1024;        // 32*16
  float* sbr  = sWp + 512;         // 32
  float* sbp  = sbr + 32;          // 16

  int tid = threadIdx.x;
  int b = blockIdx.x >> 1, sub = blockIdx.x & 1;

  {
    int u = tid;
    if (u < 1024){
      sWr[u] = __ldg(Wrel1  + (u & 31)*HID + (u >> 5));
      sWo[u] = __ldg(Wroot1 + (u & 31)*HID + (u >> 5));
    }
    if (u < 512) sWp[u] = __ldg(Wp + (u & 15)*HID + (u >> 4));
    if (u < 32)  sbr[u] = __ldg(brel1 + u);
    if (u < 16)  sbp[u] = __ldg(bp + u);
  }
  const float* hsl = g_h + (size_t)b*NPG*HID;
  for (int v = tid; v < NPG*HID; v += 1024)
    sH[(v >> 5)*33 + (v & 31)] = __ldg(hsl + v);
  __syncthreads();

  int wid = tid >> 5, lane = tid & 31;
  #pragma unroll 1
  for (int k = 0; k < 16; k++){
    int ln = wid*16 + k;
    int n  = b*NPG + sub*512 + ln;
    int start = __ldg(g_off + n), cnt = __ldg(g_cnt + n);
    float acc = 0.f;
    for (int base = 0; base < cnt; base += 32){
      int m = cnt - base; if (m > 32) m = 32;
      int idx = (lane < m) ? (int)__ldg(g_csr16 + start + base + lane) : 0;
      int i = 0;
      for (; i + 4 <= m; i += 4){
        int d0 = __shfl_sync(0xffffffffu, idx, i);
        int d1 = __shfl_sync(0xffffffffu, idx, i+1);
        int d2 = __shfl_sync(0xffffffffu, idx, i+2);
        int d3 = __shfl_sync(0xffffffffu, idx, i+3);
        float v0 = sH[d0*33 + lane];
        float v1 = sH[d1*33 + lane];
        float v2 = sH[d2*33 + lane];
        float v3 = sH[d3*33 + lane];
        acc += (v0 + v1) + (v2 + v3);
      }
      for (; i < m; i++){
        int d = __shfl_sync(0xffffffffu, idx, i);
        acc += sH[d*33 + lane];
      }
    }
    sAgg[ln*33 + lane] = acc;
  }
  __syncthreads();

  int ln = tid >> 1, half = tid & 1;
  int nl = sub*512 + ln;
  int j0 = half*16;

  float hacc[16];
  #pragma unroll
  for (int j = 0; j < 16; j++) hacc[j] = sbr[j0 + j];

  const float4* sWr4 = reinterpret_cast<const float4*>(sWr);
  const float4* sWo4 = reinterpret_cast<const float4*>(sWo);
  #pragma unroll
  for (int i = 0; i < HID; i++){
    float a  = sAgg[ln*33 + i];
    float hh = sH[nl*33 + i];
    #pragma unroll
    for (int j4 = 0; j4 < 4; j4++){
      float4 wr = sWr4[i*8 + half*4 + j4];
      float4 wo = sWo4[i*8 + half*4 + j4];
      hacc[j4*4+0] += a*wr.x + hh*wo.x;
      hacc[j4*4+1] += a*wr.y + hh*wo.y;
      hacc[j4*4+2] += a*wr.z + hh*wo.z;
      hacc[j4*4+3] += a*wr.w + hh*wo.w;
    }
  }

  float t[16];
  #pragma unroll
  for (int c = 0; c < 16; c++) t[c] = half ? 0.f : sbp[c];
  const float4* sWp4 = reinterpret_cast<const float4*>(sWp);
  #pragma unroll
  for (int il = 0; il < 16; il++){
    int i = j0 + il;
    float hv = hacc[il];
    #pragma unroll
    for (int c4 = 0; c4 < 4; c4++){
      float4 wp = sWp4[i*4 + c4];
      t[c4*4+0] += hv*wp.x;
      t[c4*4+1] += hv*wp.y;
      t[c4*4+2] += hv*wp.z;
      t[c4*4+3] += hv*wp.w;
    }
  }
  #pragma unroll
  for (int c = 0; c < 16; c++) t[c] += __shfl_xor_sync(0xffffffffu, t[c], 1);

  float mx = t[0];
  #pragma unroll
  for (int c = 1; c < 16; c++) mx = fmaxf(mx, t[c]);
  float se = 0.f;
  #pragma unroll
  for (int c = 0; c < 16; c++){ t[c] = expf(t[c] - mx); se += t[c]; }
  float inv = 1.f / se;

  __syncwarp();
  #pragma unroll
  for (int j = 0; j < 16; j++) sAgg[ln*33 + j0 + j] = hacc[j];
  if (half == 0){
    #pragma unroll
    for (int c = 0; c < 16; c++) sH[nl*33 + c] = t[c]*inv;
  }
  __syncthreads();

  size_t hoff = (size_t)(b*NPG + sub*512)*HID;
  for (int v = tid; v < 512*HID; v += 1024)
    g_h1[hoff + v] = sAgg[(v >> 5)*33 + (v & 31)];
  size_t soff = (size_t)(b*NPG + sub*512)*KC;
  for (int v = tid; v < 512*KC; v += 1024)
    g_s[soff + v] = sH[(sub*512 + (v >> 4))*33 + (v & 15)];
}

// ---------------- K45: gather AS (smem) + fused per-graph reductions ----------------
#define SMEM45 ((1024*17 + 512*17 + 512*33 + 512) * 4)
__global__ void __launch_bounds__(1024, 1) k45(){
  extern __shared__ float sm[];
  float* sS  = sm;                 // 1024*17 : staged s (full graph)
  float* sAS = sS + 1024*17;       // 512*17  : AS for this half
  float* sH1 = sAS + 512*17;       // 512*33  : staged h1 (this half)
  float* sD  = sH1 + 512*33;       // 512     : degrees (this half)

  int tid = threadIdx.x;
  int b = blockIdx.x >> 1, sub = blockIdx.x & 1;

  const float* ssl = g_s + (size_t)b*NPG*KC;
  for (int v = tid; v < NPG*KC; v += 1024)
    sS[(v >> 4)*17 + (v & 15)] = __ldg(ssl + v);
  const float* h1sl = g_h1 + (size_t)(b*NPG + sub*512)*HID;
  for (int v = tid; v < 512*HID; v += 1024)
    sH1[(v >> 5)*33 + (v & 31)] = __ldg(h1sl + v);
  if (tid < 512) sD[tid] = __ldg(g_deg + b*NPG + sub*512 + tid);
  __syncthreads();

  // gather AS[ln] = sum s[dst] over CSR
  int wid = tid >> 5, lane = tid & 31;
  int c = lane & 15, half = lane >> 4;
  #pragma unroll 1
  for (int k = 0; k < 16; k++){
    int ln = wid*16 + k;
    int n  = b*NPG + sub*512 + ln;
    int start = __ldg(g_off + n), cnt = __ldg(g_cnt + n);
    float acc = 0.f;
    for (int base = 0; base < cnt; base += 32){
      int m = cnt - base; if (m > 32) m = 32;
      int idx = (lane < m) ? (int)__ldg(g_csr16 + start + base + lane) : 0;
      int i = 0;
      for (; i + 4 <= m; i += 4){
        int d0 = __shfl_sync(0xffffffffu, idx, i + half);
        int d1 = __shfl_sync(0xffffffffu, idx, i + 2 + half);
        acc += sS[d0*17 + c] + sS[d1*17 + c];
      }
      for (; i < m; i += 2){
        int j = i + half;
        int d = __shfl_sync(0xffffffffu, idx, (j < m) ? j : 0);
        if (j < m) acc += sS[d*17 + c];
      }
    }
    acc += __shfl_xor_sync(0xffffffffu, acc, 16);
    if (lane < KC) sAS[ln*17 + lane] = acc;
  }
  __syncthreads();

  // fused reductions: group g handles 128 nodes; thread = (g, k, l)
  int g = tid >> 8, k = (tid >> 4) & 15, l = tid & 15;
  float oadj = 0.f, ssv = 0.f, o0 = 0.f, o1 = 0.f, denp = 0.f;
  int n0 = g*128;
  #pragma unroll 4
  for (int i = 0; i < 128; i++){
    int ln = n0 + i;
    int nl = sub*512 + ln;
    float sk = sS[nl*17 + k];
    oadj += sk * sAS[ln*17 + l];
    ssv  += sk * sS[nl*17 + l];
    o0   += sk * sH1[ln*33 + l];
    o1   += sk * sH1[ln*33 + 16 + l];
    if (l == 0) denp += sD[ln]*sk*sk;
  }
  atomicAdd(&g_oa[b*256 + k*16 + l], oadj);
  atomicAdd(&g_ss[b*256 + k*16 + l], ssv);
  atomicAdd(&g_out[b*512 + k*HID + l], o0);
  atomicAdd(&g_out[b*512 + k*HID + 16 + l], o1);
  if (l == 0) atomicAdd(&g_den[b], denp);
}

// ---------------- K6: per-graph finalize + loss means + reset g_cnt ----------------
__global__ void k6(const float* __restrict__ Wrel2, const float* __restrict__ brel2,
                   const float* __restrict__ Wroot2, const float* __restrict__ W2,
                   const float* __restrict__ b2, const float* __restrict__ W3,
                   const float* __restrict__ b3, float* __restrict__ out){
  int b = blockIdx.x, lane = threadIdx.x;
  __shared__ float s_oa[256], s_ss[256], s_out[512], s_d[16], s_c[16],
                   s_u[32], s_v[32], s_g[32], s_z[32];
  for (int u = lane; u < 256; u += 32){ s_oa[u] = g_oa[b*256+u]; s_ss[u] = g_ss[b*256+u]; }
  for (int u = lane; u < 512; u += 32) s_out[u] = g_out[b*512+u];
  __syncwarp();

  float diag = 0.f;
  if (lane < 16){
    diag = s_oa[lane*16 + lane];
    float rs = 0.f;
    #pragma unroll
    for (int l = 0; l < 16; l++) rs += s_oa[lane*16 + l];
    rs -= diag;
    s_d[lane] = sqrtf(fmaxf(rs, 0.f)) + 1e-15f;
    s_oa[lane*16 + lane] = 0.f;
  }
  float num = diag;
  #pragma unroll
  for (int o = 16; o > 0; o >>= 1) num += __shfl_xor_sync(0xffffffffu, num, o);

  float sq = 0.f;
  for (int u = lane; u < 256; u += 32){ float v = s_ss[u]; sq += v*v; }
  #pragma unroll
  for (int o = 16; o > 0; o >>= 1) sq += __shfl_xor_sync(0xffffffffu, sq, o);
  float nrm = sqrtf(sq);
  float osq = 0.f;
  for (int u = lane; u < 256; u += 32){
    float v = s_ss[u]/nrm - (((u >> 4) == (u & 15)) ? 0.25f : 0.f);
    osq += v*v;
  }
  #pragma unroll
  for (int o = 16; o > 0; o >>= 1) osq += __shfl_xor_sync(0xffffffffu, osq, o);
  float den = g_den[b];
  if (lane == 0){
    atomicAdd(out + NB*OUTC,     -(num/den) * (1.f/64.f));
    atomicAdd(out + NB*OUTC + 1, sqrtf(osq) * (1.f/64.f));
  }
  __syncwarp();

  if (lane < 16){
    float c = 0.f;
    #pragma unroll
    for (int kk = 0; kk < 16; kk++) c += s_oa[kk*16 + lane] / s_d[kk];
    s_c[lane] = c / s_d[lane];
  }
  __syncwarp();

  {
    float uu = 0.f, vv = 0.f;
    #pragma unroll
    for (int j = 0; j < 16; j++){
      float o = s_out[j*32 + lane];
      uu += s_c[j]*o;
      vv += o;
    }
    s_u[lane] = uu; s_v[lane] = vv;
  }
  __syncwarp();

  float gh = 16.f * brel2[lane];
  #pragma unroll
  for (int i = 0; i < 32; i++)
    gh += s_u[i]*Wrel2[lane*32 + i] + s_v[i]*Wroot2[lane*32 + i];
  s_g[lane] = gh;
  __syncwarp();

  float z = b2[lane];
  #pragma unroll
  for (int i = 0; i < 32; i++) z += s_g[i]*W2[lane*32 + i];
  z = fmaxf(z, 0.f);
  s_z[lane] = z;
  __syncwarp();

  float z2 = -1e30f;
  if (lane < OUTC){
    z2 = b3[lane];
    #pragma unroll
    for (int i = 0; i < 32; i++) z2 += s_z[i]*W3[lane*32 + i];
  }
  float m = z2;
  #pragma unroll
  for (int o = 16; o > 0; o >>= 1) m = fmaxf(m, __shfl_xor_sync(0xffffffffu, m, o));
  float e = (lane < OUTC) ? expf(z2 - m) : 0.f;
  float se = e;
  #pragma unroll
  for (int o = 16; o > 0; o >>= 1) se += __shfl_xor_sync(0xffffffffu, se, o);
  float lse = m + logf(se);
  if (lane < OUTC) out[b*OUTC + lane] = z2 - lse;

  // reset g_cnt for the next call (invariant: zero at kernel_launch entry)
  int4* c4 = reinterpret_cast<int4*>(g_cnt);
  int zb = (b*32 + lane)*8;
  #pragma unroll
  for (int q = 0; q < 8; q++) c4[zb + q] = make_int4(0,0,0,0);
}

// ---------------- launch ----------------
extern "C" void kernel_launch(void* const* d_in, const int* in_sizes, int n_in,
                              void* d_out, int out_size){
  const float* x      = (const float*)d_in[0];
  const float* W1     = (const float*)d_in[1];
  const float* b1     = (const float*)d_in[2];
  const float* Wrel1  = (const float*)d_in[3];
  const float* brel1  = (const float*)d_in[4];
  const float* Wroot1 = (const float*)d_in[5];
  const float* Wp     = (const float*)d_in[6];
  const float* bp     = (const float*)d_in[7];
  const float* Wrel2  = (const float*)d_in[8];
  const float* brel2  = (const float*)d_in[9];
  const float* Wroot2 = (const float*)d_in[10];
  const float* W2     = (const float*)d_in[11];
  const float* b2     = (const float*)d_in[12];
  const float* W3     = (const float*)d_in[13];
  const float* b3     = (const float*)d_in[14];
  const int*   ei     = (const int*)d_in[15];
  float* out = (float*)d_out;

  cudaFuncSetAttribute(k2s, cudaFuncAttributeMaxDynamicSharedMemorySize, SMEM2);
  cudaFuncSetAttribute(k45, cudaFuncAttributeMaxDynamicSharedMemorySize, SMEM45);

  k1    <<<512, 256>>>(x, W1, b1, ei, out);
  kscanA<<<64, 256>>>();
  kscanC<<<64, 256>>>();
  kb2   <<<512, 256>>>(ei);
  kfill2<<<128, 1024>>>();
  k2s   <<<128, 1024, SMEM2>>>(Wrel1, brel1, Wroot1, Wp, bp);
  k45   <<<128, 1024, SMEM45>>>();
  k6    <<<64, 32>>>(Wrel2, brel2, Wroot2, W2, b2, W3, b3, out);
}

// round 9
// speedup vs baseline: 1.0938x; 1.0938x over previous
#include <cuda_runtime.h>
#include <math.h>

#define TOT   65536
#define NB    64
#define NPG   1024
#define NE    2097152
#define INCH  128
#define HID   32
#define KC    16
#define OUTC  10
#define CAP   20480    // per-bin edge capacity (mean 16384, sd ~128)

// ---------------- scratch (static device globals; no allocation) ----------------
__device__ float g_h  [TOT*HID];    // lin1 output
__device__ float g_h1 [TOT*HID];    // conv1 output
__device__ float g_s  [TOT*KC];     // softmax assignments
__device__ float g_deg[TOT];        // out-degree per node (float)
__device__ int   g_cnt[TOT];        // per-node counts
__device__ int   g_off[TOT];        // CSR offsets (into g_csr16)
__device__ int   g_bincur[128];     // per-bin fill cursors (zero invariant)
__device__ int   g_eb  [128*CAP];   // bin-bucketed packed edges (srcLoc<<10)|dstLoc
__device__ unsigned short g_csr16[128*CAP]; // node-sorted local dst
__device__ float g_out[NB*KC*HID];  // pooled features S^T H
__device__ float g_oa [NB*KC*KC];   // pooled adjacency S^T A S
__device__ float g_ss [NB*KC*KC];   // S^T S
__device__ float g_den[NB];         // tr(S^T D S)

// ---------------- kb2: bucket edges into fixed-capacity 512-node bins ----------------
__global__ void __launch_bounds__(1024) kb2(const int* __restrict__ ei){
  __shared__ int hist[128], scur[128];
  int tid = threadIdx.x, blk = blockIdx.x;   // 128 blocks x 16384 edges
  if (tid < 128) hist[tid] = 0;
  __syncthreads();
  const int4* s4p = reinterpret_cast<const int4*>(ei) + blk*4096;
  const int4* d4p = reinterpret_cast<const int4*>(ei) + NE/4 + blk*4096;
  #pragma unroll
  for (int q = 0; q < 4; q++){
    int4 s = __ldg(s4p + q*1024 + tid);
    atomicAdd(&hist[s.x >> 9], 1);
    atomicAdd(&hist[s.y >> 9], 1);
    atomicAdd(&hist[s.z >> 9], 1);
    atomicAdd(&hist[s.w >> 9], 1);
  }
  __syncthreads();
  if (tid < 128) scur[tid] = tid*CAP + atomicAdd(&g_bincur[tid], hist[tid]);
  __syncthreads();
  #pragma unroll
  for (int q = 0; q < 4; q++){
    int4 s = __ldg(s4p + q*1024 + tid);
    int4 d = __ldg(d4p + q*1024 + tid);
    int p0 = atomicAdd(&scur[s.x >> 9], 1);
    int p1 = atomicAdd(&scur[s.y >> 9], 1);
    int p2 = atomicAdd(&scur[s.z >> 9], 1);
    int p3 = atomicAdd(&scur[s.w >> 9], 1);
    g_eb[p0] = ((s.x & 511) << 10) | (d.x & 1023);
    g_eb[p1] = ((s.y & 511) << 10) | (d.y & 1023);
    g_eb[p2] = ((s.z & 511) << 10) | (d.z & 1023);
    g_eb[p3] = ((s.w & 511) << 10) | (d.w & 1023);
  }
}

// ---------------- kfill3: per-bin counts + offsets + degrees + node-sort ----------------
__global__ void __launch_bounds__(1024) kfill3(){
  __shared__ int hist[512], curs[512], ws[16];
  int tid = threadIdx.x, bin = blockIdx.x;   // 128 blocks
  if (tid < 512) hist[tid] = 0;
  __syncthreads();
  int cnt = g_bincur[bin];
  int e0 = bin*CAP;
  for (int e = tid; e < cnt; e += 1024)
    atomicAdd(&hist[__ldg(g_eb + e0 + e) >> 10], 1);
  __syncthreads();
  int lane = tid & 31, w = tid >> 5;
  int c = 0, v = 0;
  if (tid < 512){
    c = hist[tid];
    v = c;
    #pragma unroll
    for (int o = 1; o < 32; o <<= 1){
      int t = __shfl_up_sync(0xffffffffu, v, o);
      if (lane >= o) v += t;
    }
    if (lane == 31) ws[w] = v;
  }
  __syncthreads();
  if (tid == 0){
    int run = 0;
    #pragma unroll
    for (int i = 0; i < 16; i++){ int t = ws[i]; ws[i] = run; run += t; }
  }
  __syncthreads();
  if (tid < 512){
    int excl = v - c + ws[w];
    curs[tid] = excl;
    int n = bin*512 + tid;
    g_off[n] = e0 + excl;
    g_cnt[n] = c;
    g_deg[n] = (float)c;
  }
  __syncthreads();
  for (int e = tid; e < cnt; e += 1024){
    int p = __ldg(g_eb + e0 + e);
    int pos = atomicAdd(&curs[p >> 10], 1);
    g_csr16[e0 + pos] = (unsigned short)(p & 1023);
  }
  __syncthreads();
  if (tid == 0) g_bincur[bin] = 0;   // restore invariant for next call
}

// ---------------- K1: h = x @ W1^T + b1 ; zero pooled scratch ----------------
__global__ void __launch_bounds__(256) k1(const float* __restrict__ x,
                                          const float* __restrict__ W1,
                                          const float* __restrict__ b1,
                                          float* __restrict__ out){
  __shared__ float sW[INCH*HID];   // sW[i*32+j] = W1[j*128+i]
  __shared__ float sb[HID];
  int tid = threadIdx.x;
  for (int u = tid; u < INCH*HID; u += 256){
    int i = u >> 5, j = u & 31;
    sW[u] = W1[j*INCH + i];
  }
  if (tid < HID) sb[tid] = b1[tid];

  int gid = blockIdx.x*256 + tid;
  if (gid < NB*KC*HID) g_out[gid] = 0.f;
  if (gid < NB*KC*KC){ g_oa[gid] = 0.f; g_ss[gid] = 0.f; }
  if (gid < NB) g_den[gid] = 0.f;
  if (gid == 0){ out[NB*OUTC] = 0.f; out[NB*OUTC+1] = 0.f; }
  __syncthreads();

  int base = blockIdx.x * 128;
  int rg = tid >> 3;
  int cg = tid & 7;
  int r0 = base + rg*4;

  float acc[4][4];
  #pragma unroll
  for (int k = 0; k < 4; k++)
    #pragma unroll
    for (int c = 0; c < 4; c++) acc[k][c] = sb[cg*4 + c];

  #pragma unroll 4
  for (int i4 = 0; i4 < 32; i4++){
    float4 xq[4];
    #pragma unroll
    for (int k = 0; k < 4; k++)
      xq[k] = __ldg(reinterpret_cast<const float4*>(x + (size_t)(r0+k)*INCH) + i4);
    #pragma unroll
    for (int ii = 0; ii < 4; ii++){
      int i = i4*4 + ii;
      float wv[4];
      #pragma unroll
      for (int c = 0; c < 4; c++) wv[c] = sW[i*32 + cg*4 + c];
      #pragma unroll
      for (int k = 0; k < 4; k++){
        float xs = (&xq[k].x)[ii];
        #pragma unroll
        for (int c = 0; c < 4; c++) acc[k][c] += xs * wv[c];
      }
    }
  }
  float4* h4 = reinterpret_cast<float4*>(g_h);
  #pragma unroll
  for (int k = 0; k < 4; k++)
    h4[(size_t)(r0+k)*8 + cg] = make_float4(acc[k][0],acc[k][1],acc[k][2],acc[k][3]);
}

// ---------------- K2s: smem-staged gather + conv1 + pool-softmax ----------------
#define SMEM2 ((1024*33 + 512*33 + 1024 + 1024 + 512 + 32 + 16) * 4)
__global__ void __launch_bounds__(1024, 1) k2s(const float* __restrict__ Wrel1,
                                               const float* __restrict__ brel1,
                                               const float* __restrict__ Wroot1,
                                               const float* __restrict__ Wp,
                                               const float* __restrict__ bp){
  extern __shared__ float smem[];
  float* sH   = smem;              // 1024*33
  float* sAgg = sH + 1024*33;      // 512*33
  float* sWr  = sAgg + 512*33;     // 32*32
  float* sWo  = sWr + 1024;        // 32*32
  float* sWp  = sWo + 1024;        // 32*16
  float* sbr  = sWp + 512;         // 32
  float* sbp  = sbr + 32;          // 16

  int tid = threadIdx.x;
  int b = blockIdx.x >> 1, sub = blockIdx.x & 1;

  {
    int u = tid;
    if (u < 1024){
      sWr[u] = __ldg(Wrel1  + (u & 31)*HID + (u >> 5));
      sWo[u] = __ldg(Wroot1 + (u & 31)*HID + (u >> 5));
    }
    if (u < 512) sWp[u] = __ldg(Wp + (u & 15)*HID + (u >> 4));
    if (u < 32)  sbr[u] = __ldg(brel1 + u);
    if (u < 16)  sbp[u] = __ldg(bp + u);
  }
  const float* hsl = g_h + (size_t)b*NPG*HID;
  for (int v = tid; v < NPG*HID; v += 1024)
    sH[(v >> 5)*33 + (v & 31)] = __ldg(hsl + v);
  __syncthreads();

  int wid = tid >> 5, lane = tid & 31;
  #pragma unroll 1
  for (int k = 0; k < 16; k++){
    int ln = wid*16 + k;
    int n  = b*NPG + sub*512 + ln;
    int start = __ldg(g_off + n), cnt = __ldg(g_cnt + n);
    float acc = 0.f;
    for (int base = 0; base < cnt; base += 32){
      int m = cnt - base; if (m > 32) m = 32;
      int idx = (lane < m) ? (int)__ldg(g_csr16 + start + base + lane) : 0;
      int i = 0;
      for (; i + 4 <= m; i += 4){
        int d0 = __shfl_sync(0xffffffffu, idx, i);
        int d1 = __shfl_sync(0xffffffffu, idx, i+1);
        int d2 = __shfl_sync(0xffffffffu, idx, i+2);
        int d3 = __shfl_sync(0xffffffffu, idx, i+3);
        float v0 = sH[d0*33 + lane];
        float v1 = sH[d1*33 + lane];
        float v2 = sH[d2*33 + lane];
        float v3 = sH[d3*33 + lane];
        acc += (v0 + v1) + (v2 + v3);
      }
      for (; i < m; i++){
        int d = __shfl_sync(0xffffffffu, idx, i);
        acc += sH[d*33 + lane];
      }
    }
    sAgg[ln*33 + lane] = acc;
  }
  __syncthreads();

  int ln = tid >> 1, half = tid & 1;
  int nl = sub*512 + ln;
  int j0 = half*16;

  float hacc[16];
  #pragma unroll
  for (int j = 0; j < 16; j++) hacc[j] = sbr[j0 + j];

  const float4* sWr4 = reinterpret_cast<const float4*>(sWr);
  const float4* sWo4 = reinterpret_cast<const float4*>(sWo);
  #pragma unroll
  for (int i = 0; i < HID; i++){
    float a  = sAgg[ln*33 + i];
    float hh = sH[nl*33 + i];
    #pragma unroll
    for (int j4 = 0; j4 < 4; j4++){
      float4 wr = sWr4[i*8 + half*4 + j4];
      float4 wo = sWo4[i*8 + half*4 + j4];
      hacc[j4*4+0] += a*wr.x + hh*wo.x;
      hacc[j4*4+1] += a*wr.y + hh*wo.y;
      hacc[j4*4+2] += a*wr.z + hh*wo.z;
      hacc[j4*4+3] += a*wr.w + hh*wo.w;
    }
  }

  float t[16];
  #pragma unroll
  for (int c = 0; c < 16; c++) t[c] = half ? 0.f : sbp[c];
  const float4* sWp4 = reinterpret_cast<const float4*>(sWp);
  #pragma unroll
  for (int il = 0; il < 16; il++){
    int i = j0 + il;
    float hv = hacc[il];
    #pragma unroll
    for (int c4 = 0; c4 < 4; c4++){
      float4 wp = sWp4[i*4 + c4];
      t[c4*4+0] += hv*wp.x;
      t[c4*4+1] += hv*wp.y;
      t[c4*4+2] += hv*wp.z;
      t[c4*4+3] += hv*wp.w;
    }
  }
  #pragma unroll
  for (int c = 0; c < 16; c++) t[c] += __shfl_xor_sync(0xffffffffu, t[c], 1);

  float mx = t[0];
  #pragma unroll
  for (int c = 1; c < 16; c++) mx = fmaxf(mx, t[c]);
  float se = 0.f;
  #pragma unroll
  for (int c = 0; c < 16; c++){ t[c] = expf(t[c] - mx); se += t[c]; }
  float inv = 1.f / se;

  __syncwarp();
  #pragma unroll
  for (int j = 0; j < 16; j++) sAgg[ln*33 + j0 + j] = hacc[j];
  if (half == 0){
    #pragma unroll
    for (int c = 0; c < 16; c++) sH[nl*33 + c] = t[c]*inv;
  }
  __syncthreads();

  size_t hoff = (size_t)(b*NPG + sub*512)*HID;
  for (int v = tid; v < 512*HID; v += 1024)
    g_h1[hoff + v] = sAgg[(v >> 5)*33 + (v & 31)];
  size_t soff = (size_t)(b*NPG + sub*512)*KC;
  for (int v = tid; v < 512*KC; v += 1024)
    g_s[soff + v] = sH[(sub*512 + (v >> 4))*33 + (v & 15)];
}

// ---------------- K45: gather AS (smem) + fused per-graph reductions ----------------
#define SMEM45 ((1024*17 + 512*17 + 512*33 + 512) * 4)
__global__ void __launch_bounds__(1024, 1) k45(){
  extern __shared__ float sm[];
  float* sS  = sm;                 // 1024*17
  float* sAS = sS + 1024*17;       // 512*17
  float* sH1 = sAS + 512*17;       // 512*33
  float* sD  = sH1 + 512*33;       // 512

  int tid = threadIdx.x;
  int b = blockIdx.x >> 1, sub = blockIdx.x & 1;

  const float* ssl = g_s + (size_t)b*NPG*KC;
  for (int v = tid; v < NPG*KC; v += 1024)
    sS[(v >> 4)*17 + (v & 15)] = __ldg(ssl + v);
  const float* h1sl = g_h1 + (size_t)(b*NPG + sub*512)*HID;
  for (int v = tid; v < 512*HID; v += 1024)
    sH1[(v >> 5)*33 + (v & 31)] = __ldg(h1sl + v);
  if (tid < 512) sD[tid] = __ldg(g_deg + b*NPG + sub*512 + tid);
  __syncthreads();

  int wid = tid >> 5, lane = tid & 31;
  int c = lane & 15, half = lane >> 4;
  #pragma unroll 1
  for (int k = 0; k < 16; k++){
    int ln = wid*16 + k;
    int n  = b*NPG + sub*512 + ln;
    int start = __ldg(g_off + n), cnt = __ldg(g_cnt + n);
    float acc = 0.f;
    for (int base = 0; base < cnt; base += 32){
      int m = cnt - base; if (m > 32) m = 32;
      int idx = (lane < m) ? (int)__ldg(g_csr16 + start + base + lane) : 0;
      int i = 0;
      for (; i + 4 <= m; i += 4){
        int d0 = __shfl_sync(0xffffffffu, idx, i + half);
        int d1 = __shfl_sync(0xffffffffu, idx, i + 2 + half);
        acc += sS[d0*17 + c] + sS[d1*17 + c];
      }
      for (; i < m; i += 2){
        int j = i + half;
        int d = __shfl_sync(0xffffffffu, idx, (j < m) ? j : 0);
        if (j < m) acc += sS[d*17 + c];
      }
    }
    acc += __shfl_xor_sync(0xffffffffu, acc, 16);
    if (lane < KC) sAS[ln*17 + lane] = acc;
  }
  __syncthreads();

  int g = tid >> 8, k = (tid >> 4) & 15, l = tid & 15;
  float oadj = 0.f, ssv = 0.f, o0 = 0.f, o1 = 0.f, denp = 0.f;
  int n0 = g*128;
  #pragma unroll 4
  for (int i = 0; i < 128; i++){
    int ln = n0 + i;
    int nl = sub*512 + ln;
    float sk = sS[nl*17 + k];
    oadj += sk * sAS[ln*17 + l];
    ssv  += sk * sS[nl*17 + l];
    o0   += sk * sH1[ln*33 + l];
    o1   += sk * sH1[ln*33 + 16 + l];
    if (l == 0) denp += sD[ln]*sk*sk;
  }
  atomicAdd(&g_oa[b*256 + k*16 + l], oadj);
  atomicAdd(&g_ss[b*256 + k*16 + l], ssv);
  atomicAdd(&g_out[b*512 + k*HID + l], o0);
  atomicAdd(&g_out[b*512 + k*HID + 16 + l], o1);
  if (l == 0) atomicAdd(&g_den[b], denp);
}

// ---------------- K6: per-graph finalize + loss means ----------------
__global__ void k6(const float* __restrict__ Wrel2, const float* __restrict__ brel2,
                   const float* __restrict__ Wroot2, const float* __restrict__ W2,
                   const float* __restrict__ b2, const float* __restrict__ W3,
                   const float* __restrict__ b3, float* __restrict__ out){
  int b = blockIdx.x, lane = threadIdx.x;
  __shared__ float s_oa[256], s_ss[256], s_out[512], s_d[16], s_c[16],
                   s_u[32], s_v[32], s_g[32], s_z[32];
  for (int u = lane; u < 256; u += 32){ s_oa[u] = g_oa[b*256+u]; s_ss[u] = g_ss[b*256+u]; }
  for (int u = lane; u < 512; u += 32) s_out[u] = g_out[b*512+u];
  __syncwarp();

  float diag = 0.f;
  if (lane < 16){
    diag = s_oa[lane*16 + lane];
    float rs = 0.f;
    #pragma unroll
    for (int l = 0; l < 16; l++) rs += s_oa[lane*16 + l];
    rs -= diag;
    s_d[lane] = sqrtf(fmaxf(rs, 0.f)) + 1e-15f;
    s_oa[lane*16 + lane] = 0.f;
  }
  float num = diag;
  #pragma unroll
  for (int o = 16; o > 0; o >>= 1) num += __shfl_xor_sync(0xffffffffu, num, o);

  float sq = 0.f;
  for (int u = lane; u < 256; u += 32){ float v = s_ss[u]; sq += v*v; }
  #pragma unroll
  for (int o = 16; o > 0; o >>= 1) sq += __shfl_xor_sync(0xffffffffu, sq, o);
  float nrm = sqrtf(sq);
  float osq = 0.f;
  for (int u = lane; u < 256; u += 32){
    float v = s_ss[u]/nrm - (((u >> 4) == (u & 15)) ? 0.25f : 0.f);
    osq += v*v;
  }
  #pragma unroll
  for (int o = 16; o > 0; o >>= 1) osq += __shfl_xor_sync(0xffffffffu, osq, o);
  float den = g_den[b];
  if (lane == 0){
    atomicAdd(out + NB*OUTC,     -(num/den) * (1.f/64.f));
    atomicAdd(out + NB*OUTC + 1, sqrtf(osq) * (1.f/64.f));
  }
  __syncwarp();

  if (lane < 16){
    float c = 0.f;
    #pragma unroll
    for (int kk = 0; kk < 16; kk++) c += s_oa[kk*16 + lane] / s_d[kk];
    s_c[lane] = c / s_d[lane];
  }
  __syncwarp();

  {
    float uu = 0.f, vv = 0.f;
    #pragma unroll
    for (int j = 0; j < 16; j++){
      float o = s_out[j*32 + lane];
      uu += s_c[j]*o;
      vv += o;
    }
    s_u[lane] = uu; s_v[lane] = vv;
  }
  __syncwarp();

  float gh = 16.f * brel2[lane];
  #pragma unroll
  for (int i = 0; i < 32; i++)
    gh += s_u[i]*Wrel2[lane*32 + i] + s_v[i]*Wroot2[lane*32 + i];
  s_g[lane] = gh;
  __syncwarp();

  float z = b2[lane];
  #pragma unroll
  for (int i = 0; i < 32; i++) z += s_g[i]*W2[lane*32 + i];
  z = fmaxf(z, 0.f);
  s_z[lane] = z;
  __syncwarp();

  float z2 = -1e30f;
  if (lane < OUTC){
    z2 = b3[lane];
    #pragma unroll
    for (int i = 0; i < 32; i++) z2 += s_z[i]*W3[lane*32 + i];
  }
  float m = z2;
  #pragma unroll
  for (int o = 16; o > 0; o >>= 1) m = fmaxf(m, __shfl_xor_sync(0xffffffffu, m, o));
  float e = (lane < OUTC) ? expf(z2 - m) : 0.f;
  float se = e;
  #pragma unroll
  for (int o = 16; o > 0; o >>= 1) se += __shfl_xor_sync(0xffffffffu, se, o);
  float lse = m + logf(se);
  if (lane < OUTC) out[b*OUTC + lane] = z2 - lse;
}

// ---------------- launch (single stream; graph-capture safe) ----------------
extern "C" void kernel_launch(void* const* d_in, const int* in_sizes, int n_in,
                              void* d_out, int out_size){
  const float* x      = (const float*)d_in[0];
  const float* W1     = (const float*)d_in[1];
  const float* b1     = (const float*)d_in[2];
  const float* Wrel1  = (const float*)d_in[3];
  const float* brel1  = (const float*)d_in[4];
  const float* Wroot1 = (const float*)d_in[5];
  const float* Wp     = (const float*)d_in[6];
  const float* bp     = (const float*)d_in[7];
  const float* Wrel2  = (const float*)d_in[8];
  const float* brel2  = (const float*)d_in[9];
  const float* Wroot2 = (const float*)d_in[10];
  const float* W2     = (const float*)d_in[11];
  const float* b2     = (const float*)d_in[12];
  const float* W3     = (const float*)d_in[13];
  const float* b3     = (const float*)d_in[14];
  const int*   ei     = (const int*)d_in[15];
  float* out = (float*)d_out;

  cudaFuncSetAttribute(k2s, cudaFuncAttributeMaxDynamicSharedMemorySize, SMEM2);
  cudaFuncSetAttribute(k45, cudaFuncAttributeMaxDynamicSharedMemorySize, SMEM45);

  kb2   <<<128, 1024>>>(ei);
  kfill3<<<128, 1024>>>();
  k1    <<<512, 256>>>(x, W1, b1, out);
  k2s   <<<128, 1024, SMEM2>>>(Wrel1, brel1, Wroot1, Wp, bp);
  k45   <<<128, 1024, SMEM45>>>();
  k6    <<<64, 32>>>(Wrel2, brel2, Wroot2, W2, b2, W3, b3, out);
}